// round 1
// baseline (speedup 1.0000x reference)
#include <cuda_runtime.h>

// Problem constants
#define Bn 16
#define Cc 256
#define Sn 4096   // H*W
#define C8 32     // C/8
#define C2 128    // C/2
#define Dn 1024   // down = HW/4

// Scratch (device globals; no allocation allowed)
__device__ float g_q[(size_t)Bn * C8 * Sn];     // per-batch flat [32*4096] conv layout
__device__ float g_k[(size_t)Bn * C8 * Dn];     // per-batch flat [32*1024]
__device__ float g_v[(size_t)Bn * C2 * Dn];     // per-batch flat [128*1024]
__device__ float g_attn[(size_t)Bn * Sn * Dn];  // 268MB logits
__device__ float g_cmax[Bn * Dn];               // column max (softmax over query axis)
__device__ float g_crs[Bn * Dn];                // 1 / column sum(exp)
__device__ float g_app[(size_t)Bn * Sn * C2];   // applied [4096,128] row-major per batch

// ---------------------------------------------------------------------------
// Kernel 1: query conv1x1.  y[b,o,s] = sum_c w[o,c]*x[b,c,s] + bias[o]
// block 128 threads; each thread: 4 spatial (stride 128) x 8 out channels
// grid (Sn/512, C8/8, Bn)
// ---------------------------------------------------------------------------
__global__ void conv_q_k(const float* __restrict__ x, const float* __restrict__ w,
                         const float* __restrict__ bias) {
    int b = blockIdx.z;
    int o0 = blockIdx.y * 8;
    int s0 = blockIdx.x * 512 + threadIdx.x;
    const float* xb = x + (size_t)b * Cc * Sn;

    __shared__ float ws[8 * Cc];
    for (int i = threadIdx.x; i < 8 * Cc; i += 128) ws[i] = w[o0 * Cc + i];
    __syncthreads();

    float acc[8][4];
#pragma unroll
    for (int o = 0; o < 8; o++) {
        float bb = bias[o0 + o];
#pragma unroll
        for (int t = 0; t < 4; t++) acc[o][t] = bb;
    }

#pragma unroll 4
    for (int c = 0; c < Cc; c++) {
        const float* xc = xb + c * Sn + s0;
        float x0 = xc[0], x1 = xc[128], x2 = xc[256], x3 = xc[384];
#pragma unroll
        for (int o = 0; o < 8; o++) {
            float wv = ws[o * Cc + c];
            acc[o][0] = fmaf(wv, x0, acc[o][0]);
            acc[o][1] = fmaf(wv, x1, acc[o][1]);
            acc[o][2] = fmaf(wv, x2, acc[o][2]);
            acc[o][3] = fmaf(wv, x3, acc[o][3]);
        }
    }

    float* ob = g_q + (size_t)b * C8 * Sn;
#pragma unroll
    for (int o = 0; o < 8; o++)
#pragma unroll
        for (int t = 0; t < 4; t++)
            ob[(size_t)(o0 + o) * Sn + s0 + t * 128] = acc[o][t];
}

// ---------------------------------------------------------------------------
// Kernel 2: conv1x1 + 2x2 maxpool (key: which=0 -> g_k, O=32; value: which=1 -> g_v, O=128)
// Each thread: one pooled position (computes 4 conv results, maxes), 16 out channels.
// grid (Dn/128, O/16, Bn), block 128
// ---------------------------------------------------------------------------
__global__ void conv_pool_k(const float* __restrict__ x, const float* __restrict__ w,
                            const float* __restrict__ bias, int which) {
    float* outp = which ? g_v : g_k;
    int O = which ? C2 : C8;

    int b = blockIdx.z;
    int o0 = blockIdx.y * 16;
    int p = blockIdx.x * 128 + threadIdx.x;
    int ph = p >> 5, pw = p & 31;
    int s00 = ph * 128 + pw * 2;  // (2ph)*64 + 2pw

    const float* xb = x + (size_t)b * Cc * Sn;

    __shared__ float ws[16 * Cc];
    for (int i = threadIdx.x; i < 16 * Cc; i += 128) ws[i] = w[o0 * Cc + i];
    __syncthreads();

    float a0[16], a1[16], a2[16], a3[16];
#pragma unroll
    for (int o = 0; o < 16; o++) {
        float bb = bias[o0 + o];
        a0[o] = bb; a1[o] = bb; a2[o] = bb; a3[o] = bb;
    }

#pragma unroll 4
    for (int c = 0; c < Cc; c++) {
        const float* xc = xb + c * Sn + s00;
        float2 xa = *(const float2*)(xc);
        float2 xc2 = *(const float2*)(xc + 64);
#pragma unroll
        for (int o = 0; o < 16; o++) {
            float wv = ws[o * Cc + c];
            a0[o] = fmaf(wv, xa.x, a0[o]);
            a1[o] = fmaf(wv, xa.y, a1[o]);
            a2[o] = fmaf(wv, xc2.x, a2[o]);
            a3[o] = fmaf(wv, xc2.y, a3[o]);
        }
    }

    float* ob = outp + (size_t)b * O * Dn;
#pragma unroll
    for (int o = 0; o < 16; o++) {
        float m = fmaxf(fmaxf(a0[o], a1[o]), fmaxf(a2[o], a3[o]));
        ob[(size_t)(o0 + o) * Dn + p] = m;
    }
}

// ---------------------------------------------------------------------------
// Kernel 3: attn logits GEMM.  attn[b,l,j] = dot(qflat[l*32..], kflat[j*32..], 32)
// 64x64 tile, K=32, 256 threads, 4x4 micro-tile.
// grid (Dn/64, Sn/64, Bn)
// ---------------------------------------------------------------------------
__global__ void attn_gemm_k() {
    int b = blockIdx.z;
    int l0 = blockIdx.y * 64;
    int j0 = blockIdx.x * 64;
    const float* A = g_q + (size_t)b * C8 * Sn;   // row l: 32 contiguous
    const float* Bm = g_k + (size_t)b * C8 * Dn;  // row j: 32 contiguous
    float* Cb = g_attn + (size_t)b * Sn * Dn;

    __shared__ float As[32 * 68];  // transposed: As[kk*68 + row]
    __shared__ float Bs[32 * 68];

    int tid = threadIdx.x;
#pragma unroll
    for (int t = 0; t < 2; t++) {
        int ff = tid + t * 256;
        int row = ff >> 3, kg = (ff & 7) * 4;
        float4 av = *(const float4*)(A + (size_t)(l0 + row) * 32 + kg);
        As[(kg + 0) * 68 + row] = av.x;
        As[(kg + 1) * 68 + row] = av.y;
        As[(kg + 2) * 68 + row] = av.z;
        As[(kg + 3) * 68 + row] = av.w;
        float4 bv = *(const float4*)(Bm + (size_t)(j0 + row) * 32 + kg);
        Bs[(kg + 0) * 68 + row] = bv.x;
        Bs[(kg + 1) * 68 + row] = bv.y;
        Bs[(kg + 2) * 68 + row] = bv.z;
        Bs[(kg + 3) * 68 + row] = bv.w;
    }
    __syncthreads();

    int ty = tid >> 4, tx = tid & 15;
    float acc[4][4];
#pragma unroll
    for (int i = 0; i < 4; i++)
#pragma unroll
        for (int j = 0; j < 4; j++) acc[i][j] = 0.f;

#pragma unroll
    for (int kk = 0; kk < 32; kk++) {
        float4 a4 = *(const float4*)&As[kk * 68 + ty * 4];
        float4 b4 = *(const float4*)&Bs[kk * 68 + tx * 4];
        float a[4] = {a4.x, a4.y, a4.z, a4.w};
        float bb[4] = {b4.x, b4.y, b4.z, b4.w};
#pragma unroll
        for (int i = 0; i < 4; i++)
#pragma unroll
            for (int j = 0; j < 4; j++) acc[i][j] = fmaf(a[i], bb[j], acc[i][j]);
    }

#pragma unroll
    for (int i = 0; i < 4; i++) {
        float4 o;
        o.x = acc[i][0]; o.y = acc[i][1]; o.z = acc[i][2]; o.w = acc[i][3];
        *(float4*)(Cb + (size_t)(l0 + ty * 4 + i) * Dn + j0 + tx * 4) = o;
    }
}

// ---------------------------------------------------------------------------
// Kernel 4: column softmax stats (over query axis l).  Online max/sum per (b,j).
// block (128,4): tx -> column j, ty -> 1024-row chunk; smem merge.
// grid (Dn/128, Bn)
// ---------------------------------------------------------------------------
__global__ void stats_k() {
    int b = blockIdx.y;
    int tx = threadIdx.x;
    int ty = threadIdx.y;
    int j = blockIdx.x * 128 + tx;
    const float* col = g_attn + (size_t)b * Sn * Dn + (size_t)ty * 1024 * Dn + j;

    float m = -1e30f, s = 0.f;
    for (int r = 0; r < 1024; r += 4) {
        float v0 = col[(size_t)(r + 0) * Dn];
        float v1 = col[(size_t)(r + 1) * Dn];
        float v2 = col[(size_t)(r + 2) * Dn];
        float v3 = col[(size_t)(r + 3) * Dn];
#define UPD(vv) { float mn_ = fmaxf(m, (vv)); s = fmaf(s, __expf(m - mn_), __expf((vv) - mn_)); m = mn_; }
        UPD(v0) UPD(v1) UPD(v2) UPD(v3)
#undef UPD
    }

    __shared__ float sm[4][128], ssum[4][128];
    sm[ty][tx] = m;
    ssum[ty][tx] = s;
    __syncthreads();
    if (ty == 0) {
#pragma unroll
        for (int t = 1; t < 4; t++) {
            float m2 = sm[t][tx], s2 = ssum[t][tx];
            float mn = fmaxf(m, m2);
            s = s * __expf(m - mn) + s2 * __expf(m2 - mn);
            m = mn;
        }
        g_cmax[b * Dn + j] = m;
        g_crs[b * Dn + j] = 1.f / s;
    }
}

// ---------------------------------------------------------------------------
// Kernel 5: applied GEMM.  app[b,l,c] = sum_j exp(attn[l,j]-max[j]) * (v[j,c]/sum[j])
// 128(l) x 128(c=all) tile, K chunks of 16, 256 threads, 8x8 micro.
// grid (Sn/128, Bn)
// ---------------------------------------------------------------------------
__global__ void applied_gemm_k() {
    int b = blockIdx.y;
    int l0 = blockIdx.x * 128;
    const float* Ab = g_attn + (size_t)b * Sn * Dn;
    const float* Vb = g_v + (size_t)b * C2 * Dn;  // flat: row j -> [j*128 ..]
    const float* cmax = g_cmax + b * Dn;
    const float* crs = g_crs + b * Dn;

    __shared__ float As[16 * 132];  // transposed: As[kk*132 + row], 528B row stride (16B mult)
    __shared__ float Bs[16 * 128];  // Bs[kk*128 + c]

    int tid = threadIdx.x;
    int ty = tid >> 4, tx = tid & 15;
    float acc[8][8];
#pragma unroll
    for (int i = 0; i < 8; i++)
#pragma unroll
        for (int j = 0; j < 8; j++) acc[i][j] = 0.f;

    for (int jc = 0; jc < Dn; jc += 16) {
        // A tile: 128 rows x 16 k, exp applied at load
#pragma unroll
        for (int t = 0; t < 2; t++) {
            int ff = tid + t * 256;
            int row = ff >> 2, kg = (ff & 3) * 4;
            float4 av = *(const float4*)(Ab + (size_t)(l0 + row) * Dn + jc + kg);
            float4 cm = *(const float4*)(cmax + jc + kg);
            As[(kg + 0) * 132 + row] = __expf(av.x - cm.x);
            As[(kg + 1) * 132 + row] = __expf(av.y - cm.y);
            As[(kg + 2) * 132 + row] = __expf(av.z - cm.z);
            As[(kg + 3) * 132 + row] = __expf(av.w - cm.w);
        }
        // B tile: 16 rows x 128 c, scaled by 1/sum
#pragma unroll
        for (int t = 0; t < 2; t++) {
            int ff = tid + t * 256;
            int kk = ff >> 5, c4 = (ff & 31) * 4;
            float4 bv = *(const float4*)(Vb + (size_t)(jc + kk) * C2 + c4);
            float sc = crs[jc + kk];
            bv.x *= sc; bv.y *= sc; bv.z *= sc; bv.w *= sc;
            *(float4*)&Bs[kk * 128 + c4] = bv;
        }
        __syncthreads();

#pragma unroll
        for (int kk = 0; kk < 16; kk++) {
            float4 a0 = *(const float4*)&As[kk * 132 + ty * 8];
            float4 a1 = *(const float4*)&As[kk * 132 + ty * 8 + 4];
            float4 b0 = *(const float4*)&Bs[kk * 128 + tx * 8];
            float4 b1 = *(const float4*)&Bs[kk * 128 + tx * 8 + 4];
            float a[8] = {a0.x, a0.y, a0.z, a0.w, a1.x, a1.y, a1.z, a1.w};
            float bb[8] = {b0.x, b0.y, b0.z, b0.w, b1.x, b1.y, b1.z, b1.w};
#pragma unroll
            for (int i = 0; i < 8; i++)
#pragma unroll
                for (int j = 0; j < 8; j++) acc[i][j] = fmaf(a[i], bb[j], acc[i][j]);
        }
        __syncthreads();
    }

    float* Ob = g_app + (size_t)b * Sn * C2;
#pragma unroll
    for (int i = 0; i < 8; i++) {
        int l = l0 + ty * 8 + i;
        float4 o0, o1;
        o0.x = acc[i][0]; o0.y = acc[i][1]; o0.z = acc[i][2]; o0.w = acc[i][3];
        o1.x = acc[i][4]; o1.y = acc[i][5]; o1.z = acc[i][6]; o1.w = acc[i][7];
        *(float4*)(Ob + (size_t)l * C2 + tx * 8) = o0;
        *(float4*)(Ob + (size_t)l * C2 + tx * 8 + 4) = o1;
    }
}

// ---------------------------------------------------------------------------
// Kernel 6: output conv + residual.
// out[b,o,sp] = gamma*(sum_co w2[o,co]*appflat[co*4096+sp] + b2[o]) + x[b,o,sp]
// 64(o) x 128(sp) tile, K=128 in chunks of 32, 256 threads, 4x8 micro.
// grid (Sn/128, 256/64, Bn)
// ---------------------------------------------------------------------------
__global__ void out_conv_k(const float* __restrict__ x, const float* __restrict__ w2,
                           const float* __restrict__ b2, const float* __restrict__ gamma,
                           float* __restrict__ out) {
    int b = blockIdx.z;
    int o0 = blockIdx.y * 64;
    int sp0 = blockIdx.x * 128;
    const float* Ap = g_app + (size_t)b * Sn * C2;  // read flat as [co*4096 + sp]

    __shared__ float Ws[32 * 68];   // transposed: Ws[kk*68 + o_row]
    __shared__ float Bs2[32 * 128]; // Bs2[kk*128 + sp]

    int tid = threadIdx.x;
    int ty = tid >> 4, tx = tid & 15;
    float acc[4][8];
#pragma unroll
    for (int i = 0; i < 4; i++)
#pragma unroll
        for (int j = 0; j < 8; j++) acc[i][j] = 0.f;

    for (int kc = 0; kc < C2; kc += 32) {
#pragma unroll
        for (int t = 0; t < 2; t++) {
            int ff = tid + t * 256;
            int row = ff >> 3, kg = (ff & 7) * 4;
            float4 wv = *(const float4*)(w2 + (size_t)(o0 + row) * C2 + kc + kg);
            Ws[(kg + 0) * 68 + row] = wv.x;
            Ws[(kg + 1) * 68 + row] = wv.y;
            Ws[(kg + 2) * 68 + row] = wv.z;
            Ws[(kg + 3) * 68 + row] = wv.w;
        }
#pragma unroll
        for (int t = 0; t < 4; t++) {
            int ff = tid + t * 256;
            int kk = ff >> 5, c4 = (ff & 31) * 4;
            *(float4*)&Bs2[kk * 128 + c4] =
                *(const float4*)(Ap + (size_t)(kc + kk) * Sn + sp0 + c4);
        }
        __syncthreads();

#pragma unroll
        for (int kk = 0; kk < 32; kk++) {
            float4 a4 = *(const float4*)&Ws[kk * 68 + ty * 4];
            float4 b0 = *(const float4*)&Bs2[kk * 128 + tx * 8];
            float4 b1 = *(const float4*)&Bs2[kk * 128 + tx * 8 + 4];
            float a[4] = {a4.x, a4.y, a4.z, a4.w};
            float bb[8] = {b0.x, b0.y, b0.z, b0.w, b1.x, b1.y, b1.z, b1.w};
#pragma unroll
            for (int i = 0; i < 4; i++)
#pragma unroll
                for (int j = 0; j < 8; j++) acc[i][j] = fmaf(a[i], bb[j], acc[i][j]);
        }
        __syncthreads();
    }

    float g = gamma[0];
#pragma unroll
    for (int i = 0; i < 4; i++) {
        int o = o0 + ty * 4 + i;
        float bb = b2[o];
        const float* xr = x + (size_t)b * Cc * Sn + (size_t)o * Sn + sp0 + tx * 8;
        float* orow = out + (size_t)b * Cc * Sn + (size_t)o * Sn + sp0 + tx * 8;
#pragma unroll
        for (int j = 0; j < 8; j++) {
            orow[j] = fmaf(g, acc[i][j] + bb, xr[j]);
        }
    }
}

// ---------------------------------------------------------------------------
extern "C" void kernel_launch(void* const* d_in, const int* in_sizes, int n_in,
                              void* d_out, int out_size) {
    const float* x   = (const float*)d_in[0];
    const float* qw  = (const float*)d_in[1];
    const float* qb  = (const float*)d_in[2];
    const float* kw  = (const float*)d_in[3];
    const float* kb  = (const float*)d_in[4];
    const float* vw  = (const float*)d_in[5];
    const float* vb  = (const float*)d_in[6];
    const float* v2w = (const float*)d_in[7];
    const float* v2b = (const float*)d_in[8];
    const float* gm  = (const float*)d_in[9];
    float* out = (float*)d_out;

    conv_q_k<<<dim3(8, 4, Bn), 128>>>(x, qw, qb);
    conv_pool_k<<<dim3(8, 2, Bn), 128>>>(x, kw, kb, 0);   // key  -> g_k (O=32)
    conv_pool_k<<<dim3(8, 8, Bn), 128>>>(x, vw, vb, 1);   // value-> g_v (O=128)
    attn_gemm_k<<<dim3(Dn / 64, Sn / 64, Bn), 256>>>();
    stats_k<<<dim3(Dn / 128, Bn), dim3(128, 4)>>>();
    applied_gemm_k<<<dim3(Sn / 128, Bn), 256>>>();
    out_conv_k<<<dim3(Sn / 128, Cc / 64, Bn), 256>>>(x, v2w, v2b, gm, out);
}

// round 2
// speedup vs baseline: 1.2080x; 1.2080x over previous
#include <cuda_runtime.h>

#define Bn 16
#define Cc 256
#define Sn 4096   // H*W
#define C8 32     // C/8
#define C2 128    // C/2
#define Dn 1024   // down = HW/4

typedef unsigned long long ull;

// ---- packed fp32x2 helpers (sm_103a FFMA2 path) ----
__device__ __forceinline__ ull ffma2(ull a, ull b, ull c) {
    ull d;
    asm("fma.rn.f32x2 %0, %1, %2, %3;" : "=l"(d) : "l"(a), "l"(b), "l"(c));
    return d;
}
__device__ __forceinline__ ull dup2(float v) {
    ull d;
    asm("mov.b64 %0, {%1, %1};" : "=l"(d) : "f"(v));
    return d;
}
__device__ __forceinline__ float2 upk(ull v) {
    float2 r;
    asm("mov.b64 {%0, %1}, %2;" : "=f"(r.x), "=f"(r.y) : "l"(v));
    return r;
}

// ---- scratch (device globals; no allocation allowed) ----
__device__ float g_q[(size_t)Bn * C8 * Sn];
__device__ float g_k[(size_t)Bn * C8 * Dn];
__device__ float g_v[(size_t)Bn * C2 * Dn];
__device__ float g_attn[(size_t)Bn * Sn * Dn];  // 268MB logits
__device__ float g_cmax[Bn * Dn];
__device__ float g_crs[Bn * Dn];
__device__ float g_app[(size_t)Bn * Sn * C2];

// ---------------------------------------------------------------------------
// Fused conv: computes q (32ch, full res), k (32ch, pooled), v (128ch, pooled)
// as one GEMM  Y[192, 4096] = W[192,256] * X[256,4096]  per batch, with a
// pooled epilogue. Spatial tile = 128 consecutive = two image rows (contains
// 32 complete 2x2 pooling quads). o-tile = 64.
// grid (32 spatial tiles, 3 o-tiles, Bn), block 128 threads, micro 8o x 8sp.
// ---------------------------------------------------------------------------
__global__ __launch_bounds__(128) void conv_all_k(
    const float* __restrict__ x,
    const float* __restrict__ qw, const float* __restrict__ qb,
    const float* __restrict__ kw, const float* __restrict__ kb,
    const float* __restrict__ vw, const float* __restrict__ vb) {
    int b = blockIdx.z, ot = blockIdx.y, st = blockIdx.x;
    int s0 = st * 128;
    int t = threadIdx.x;

    __shared__ __align__(16) union {
        struct { float Ws[2][16][68]; float Xs[2][16][128]; } p;
        float Cs[64][128];
    } sm;

    // weight loader mapping: row = t>>1 (0..63), kg = (t&1)*8
    int wrow = t >> 1;
    int wkg = (t & 1) << 3;
    int gch = ot * 64 + wrow;
    const float* wsrc;
    if (gch < 32) wsrc = qw + (size_t)gch * Cc;
    else if (gch < 64) wsrc = kw + (size_t)(gch - 32) * Cc;
    else wsrc = vw + (size_t)(gch - 64) * Cc;
    wsrc += wkg;

    // x loader mapping: kk = t>>3 (0..15), sg = (t&7)*16
    int xkk = t >> 3;
    int xsg = (t & 7) << 4;
    const float* xsrc = x + (size_t)b * Cc * Sn + (size_t)xkk * Sn + s0 + xsg;

    int ty = t >> 4, tx = t & 15;

    ull acc[8][4];
#pragma unroll
    for (int i = 0; i < 8; i++)
#pragma unroll
        for (int j = 0; j < 4; j++) acc[i][j] = 0ULL;

    // preload chunk 0
    {
#pragma unroll
        for (int u = 0; u < 2; u++) {
            float4 v = *(const float4*)(wsrc + u * 4);
            sm.p.Ws[0][wkg + u * 4 + 0][wrow] = v.x;
            sm.p.Ws[0][wkg + u * 4 + 1][wrow] = v.y;
            sm.p.Ws[0][wkg + u * 4 + 2][wrow] = v.z;
            sm.p.Ws[0][wkg + u * 4 + 3][wrow] = v.w;
        }
#pragma unroll
        for (int u = 0; u < 4; u++)
            *(float4*)&sm.p.Xs[0][xkk][xsg + u * 4] = *(const float4*)(xsrc + u * 4);
    }
    __syncthreads();

    for (int ch = 0; ch < 16; ch++) {
        int cb = ch & 1;
        float4 wpre[2], xpre[4];
        if (ch < 15) {
            const float* wp = wsrc + (ch + 1) * 16;
            wpre[0] = *(const float4*)(wp);
            wpre[1] = *(const float4*)(wp + 4);
            const float* xp = xsrc + (size_t)(ch + 1) * 16 * Sn;
#pragma unroll
            for (int u = 0; u < 4; u++) xpre[u] = *(const float4*)(xp + u * 4);
        }
#pragma unroll
        for (int kk = 0; kk < 16; kk++) {
            float4 a0 = *(const float4*)&sm.p.Ws[cb][kk][ty * 8];
            float4 a1 = *(const float4*)&sm.p.Ws[cb][kk][ty * 8 + 4];
            ulonglong2 b0 = *(const ulonglong2*)&sm.p.Xs[cb][kk][tx * 8];
            ulonglong2 b1 = *(const ulonglong2*)&sm.p.Xs[cb][kk][tx * 8 + 4];
            ull bp[4] = {b0.x, b0.y, b1.x, b1.y};
            float aa[8] = {a0.x, a0.y, a0.z, a0.w, a1.x, a1.y, a1.z, a1.w};
#pragma unroll
            for (int i = 0; i < 8; i++) {
                ull ad = dup2(aa[i]);
#pragma unroll
                for (int j = 0; j < 4; j++) acc[i][j] = ffma2(ad, bp[j], acc[i][j]);
            }
        }
        if (ch < 15) {
            int nb = cb ^ 1;
#pragma unroll
            for (int u = 0; u < 2; u++) {
                sm.p.Ws[nb][wkg + u * 4 + 0][wrow] = (&wpre[u].x)[0];
                sm.p.Ws[nb][wkg + u * 4 + 1][wrow] = (&wpre[u].x)[1];
                sm.p.Ws[nb][wkg + u * 4 + 2][wrow] = (&wpre[u].x)[2];
                sm.p.Ws[nb][wkg + u * 4 + 3][wrow] = (&wpre[u].x)[3];
            }
#pragma unroll
            for (int u = 0; u < 4; u++)
                *(float4*)&sm.p.Xs[nb][xkk][xsg + u * 4] = xpre[u];
        }
        __syncthreads();
    }

    // spill accumulators to Cs (union reuse)
#pragma unroll
    for (int i = 0; i < 8; i++) {
        ulonglong2 u0, u1;
        u0.x = acc[i][0]; u0.y = acc[i][1];
        u1.x = acc[i][2]; u1.y = acc[i][3];
        *(ulonglong2*)&sm.Cs[ty * 8 + i][tx * 8] = u0;
        *(ulonglong2*)&sm.Cs[ty * 8 + i][tx * 8 + 4] = u1;
    }
    __syncthreads();

    if (ot == 0) {
        // q: rows 0..31, direct write
#pragma unroll
        for (int i = 0; i < 8; i++) {
            int o = i * 4 + (t >> 5);
            int sp = (t & 31) * 4;
            float4 v = *(const float4*)&sm.Cs[o][sp];
            float bb = qb[o];
            v.x += bb; v.y += bb; v.z += bb; v.w += bb;
            *(float4*)(g_q + (size_t)b * C8 * Sn + (size_t)o * Sn + s0 + sp) = v;
        }
        // k: rows 32..63, pooled
        {
            int o = 32 + (t >> 2);
            int qcb = (t & 3) * 8;
            float bb = kb[o - 32];
            float* dst = g_k + (size_t)b * C8 * Dn + (size_t)(o - 32) * Dn + st * 32;
#pragma unroll
            for (int jj = 0; jj < 8; jj++) {
                int qc = qcb + jj;
                float m = fmaxf(fmaxf(sm.Cs[o][2 * qc], sm.Cs[o][2 * qc + 1]),
                                fmaxf(sm.Cs[o][64 + 2 * qc], sm.Cs[o][64 + 2 * qc + 1]));
                dst[qc] = m + bb;
            }
        }
    } else {
        int vg0 = (ot - 1) * 64;
        int o = t >> 1;
        int qcb = (t & 1) * 16;
        float bb = vb[vg0 + o];
        float* dst = g_v + (size_t)b * C2 * Dn + (size_t)(vg0 + o) * Dn + st * 32;
#pragma unroll
        for (int jj = 0; jj < 16; jj++) {
            int qc = qcb + jj;
            float m = fmaxf(fmaxf(sm.Cs[o][2 * qc], sm.Cs[o][2 * qc + 1]),
                            fmaxf(sm.Cs[o][64 + 2 * qc], sm.Cs[o][64 + 2 * qc + 1]));
            dst[qc] = m + bb;
        }
    }
}

// ---------------------------------------------------------------------------
// attn logits: attn[b,l,j] = dot(qflat[l*32..], kflat[j*32..], 32)
// tile 128x128, 256 threads, micro 8x8 (f32x2 pairs over j), K=32 one-shot.
// grid (Dn/128, Sn/128, Bn)
// ---------------------------------------------------------------------------
__global__ __launch_bounds__(256) void attn_gemm_k() {
    int b = blockIdx.z, l0 = blockIdx.y * 128, j0 = blockIdx.x * 128;
    __shared__ __align__(16) float As[32][132];
    __shared__ __align__(16) float Bs[32][128];
    int t = threadIdx.x;
    int row = t >> 1, kg = (t & 1) * 16;
    const float* ar = g_q + (size_t)b * C8 * Sn + (size_t)(l0 + row) * 32 + kg;
    const float* br = g_k + (size_t)b * C8 * Dn + (size_t)(j0 + row) * 32 + kg;
#pragma unroll
    for (int u = 0; u < 4; u++) {
        float4 v = *(const float4*)(ar + u * 4);
        As[kg + u * 4 + 0][row] = v.x;
        As[kg + u * 4 + 1][row] = v.y;
        As[kg + u * 4 + 2][row] = v.z;
        As[kg + u * 4 + 3][row] = v.w;
        float4 w = *(const float4*)(br + u * 4);
        Bs[kg + u * 4 + 0][row] = w.x;
        Bs[kg + u * 4 + 1][row] = w.y;
        Bs[kg + u * 4 + 2][row] = w.z;
        Bs[kg + u * 4 + 3][row] = w.w;
    }
    __syncthreads();

    int ty = t >> 4, tx = t & 15;
    ull acc[8][4];
#pragma unroll
    for (int i = 0; i < 8; i++)
#pragma unroll
        for (int j = 0; j < 4; j++) acc[i][j] = 0ULL;

#pragma unroll
    for (int kk = 0; kk < 32; kk++) {
        float4 a0 = *(const float4*)&As[kk][ty * 8];
        float4 a1 = *(const float4*)&As[kk][ty * 8 + 4];
        ulonglong2 b0 = *(const ulonglong2*)&Bs[kk][tx * 8];
        ulonglong2 b1 = *(const ulonglong2*)&Bs[kk][tx * 8 + 4];
        ull bp[4] = {b0.x, b0.y, b1.x, b1.y};
        float aa[8] = {a0.x, a0.y, a0.z, a0.w, a1.x, a1.y, a1.z, a1.w};
#pragma unroll
        for (int i = 0; i < 8; i++) {
            ull ad = dup2(aa[i]);
#pragma unroll
            for (int j = 0; j < 4; j++) acc[i][j] = ffma2(ad, bp[j], acc[i][j]);
        }
    }

#pragma unroll
    for (int i = 0; i < 8; i++) {
        float* cr = g_attn + (size_t)b * Sn * Dn + (size_t)(l0 + ty * 8 + i) * Dn + j0 + tx * 8;
        ulonglong2 u0, u1;
        u0.x = acc[i][0]; u0.y = acc[i][1];
        u1.x = acc[i][2]; u1.y = acc[i][3];
        *(ulonglong2*)cr = u0;
        *(ulonglong2*)(cr + 4) = u1;
    }
}

// ---------------------------------------------------------------------------
// column softmax stats (over query axis l)
// ---------------------------------------------------------------------------
__global__ void stats_k() {
    int b = blockIdx.y;
    int tx = threadIdx.x;
    int ty = threadIdx.y;
    int j = blockIdx.x * 128 + tx;
    const float* col = g_attn + (size_t)b * Sn * Dn + (size_t)ty * 1024 * Dn + j;

    float m = -1e30f, s = 0.f;
    for (int r = 0; r < 1024; r += 4) {
        float v0 = col[(size_t)(r + 0) * Dn];
        float v1 = col[(size_t)(r + 1) * Dn];
        float v2 = col[(size_t)(r + 2) * Dn];
        float v3 = col[(size_t)(r + 3) * Dn];
#define UPD(vv) { float mn_ = fmaxf(m, (vv)); s = fmaf(s, __expf(m - mn_), __expf((vv) - mn_)); m = mn_; }
        UPD(v0) UPD(v1) UPD(v2) UPD(v3)
#undef UPD
    }

    __shared__ float smx[4][128], ssum[4][128];
    smx[ty][tx] = m;
    ssum[ty][tx] = s;
    __syncthreads();
    if (ty == 0) {
#pragma unroll
        for (int tt = 1; tt < 4; tt++) {
            float m2 = smx[tt][tx], s2 = ssum[tt][tx];
            float mn = fmaxf(m, m2);
            s = s * __expf(m - mn) + s2 * __expf(m2 - mn);
            m = mn;
        }
        g_cmax[b * Dn + j] = m;
        g_crs[b * Dn + j] = 1.f / s;
    }
}

// ---------------------------------------------------------------------------
// applied GEMM: app[b,l,c] = sum_j exp(attn[l,j]-max[j]) * (v[j,c]/sum[j])
// tile 128l x 128c, 256 threads, micro 8x8 f32x2, K=1024 chunks 16, dbl-buf.
// grid (Sn/128, Bn)
// ---------------------------------------------------------------------------
__global__ __launch_bounds__(256) void applied_gemm_k() {
    int b = blockIdx.y, l0 = blockIdx.x * 128;
    __shared__ __align__(16) float As[2][16][132];
    __shared__ __align__(16) float Bs[2][16][128];
    int t = threadIdx.x;

    int arow = t >> 1, akg = (t & 1) * 8;
    const float* asrc = g_attn + (size_t)b * Sn * Dn + (size_t)(l0 + arow) * Dn + akg;
    const float* cmaxp = g_cmax + b * Dn + akg;
    int bkk = t >> 4, bcg = (t & 15) * 8;
    const float* vbase = g_v + (size_t)b * C2 * Dn;  // flat [j*128 + c]
    const float* crsp = g_crs + b * Dn;

    int ty = t >> 4, tx = t & 15;
    ull acc[8][4];
#pragma unroll
    for (int i = 0; i < 8; i++)
#pragma unroll
        for (int j = 0; j < 4; j++) acc[i][j] = 0ULL;

    // preload chunk 0
    {
        float4 pa0 = *(const float4*)(asrc);
        float4 pa1 = *(const float4*)(asrc + 4);
        float4 cm0 = *(const float4*)(cmaxp);
        float4 cm1 = *(const float4*)(cmaxp + 4);
        As[0][akg + 0][arow] = __expf(pa0.x - cm0.x);
        As[0][akg + 1][arow] = __expf(pa0.y - cm0.y);
        As[0][akg + 2][arow] = __expf(pa0.z - cm0.z);
        As[0][akg + 3][arow] = __expf(pa0.w - cm0.w);
        As[0][akg + 4][arow] = __expf(pa1.x - cm1.x);
        As[0][akg + 5][arow] = __expf(pa1.y - cm1.y);
        As[0][akg + 6][arow] = __expf(pa1.z - cm1.z);
        As[0][akg + 7][arow] = __expf(pa1.w - cm1.w);
        float sc = crsp[bkk];
        const float* vp = vbase + (size_t)bkk * C2 + bcg;
        float4 pb0 = *(const float4*)(vp);
        float4 pb1 = *(const float4*)(vp + 4);
        pb0.x *= sc; pb0.y *= sc; pb0.z *= sc; pb0.w *= sc;
        pb1.x *= sc; pb1.y *= sc; pb1.z *= sc; pb1.w *= sc;
        *(float4*)&Bs[0][bkk][bcg] = pb0;
        *(float4*)&Bs[0][bkk][bcg + 4] = pb1;
    }
    __syncthreads();

    for (int ch = 0; ch < 64; ch++) {
        int cb = ch & 1;
        float4 pa0, pa1, cm0, cm1, pb0, pb1;
        float sc;
        if (ch < 63) {
            int jn = (ch + 1) * 16;
            pa0 = *(const float4*)(asrc + jn);
            pa1 = *(const float4*)(asrc + jn + 4);
            cm0 = *(const float4*)(cmaxp + jn);
            cm1 = *(const float4*)(cmaxp + jn + 4);
            sc = crsp[jn + bkk];
            const float* vp = vbase + (size_t)(jn + bkk) * C2 + bcg;
            pb0 = *(const float4*)(vp);
            pb1 = *(const float4*)(vp + 4);
        }
#pragma unroll
        for (int kk = 0; kk < 16; kk++) {
            float4 a0 = *(const float4*)&As[cb][kk][ty * 8];
            float4 a1 = *(const float4*)&As[cb][kk][ty * 8 + 4];
            ulonglong2 b0 = *(const ulonglong2*)&Bs[cb][kk][tx * 8];
            ulonglong2 b1 = *(const ulonglong2*)&Bs[cb][kk][tx * 8 + 4];
            ull bp[4] = {b0.x, b0.y, b1.x, b1.y};
            float aa[8] = {a0.x, a0.y, a0.z, a0.w, a1.x, a1.y, a1.z, a1.w};
#pragma unroll
            for (int i = 0; i < 8; i++) {
                ull ad = dup2(aa[i]);
#pragma unroll
                for (int j = 0; j < 4; j++) acc[i][j] = ffma2(ad, bp[j], acc[i][j]);
            }
        }
        if (ch < 63) {
            int nb = cb ^ 1;
            As[nb][akg + 0][arow] = __expf(pa0.x - cm0.x);
            As[nb][akg + 1][arow] = __expf(pa0.y - cm0.y);
            As[nb][akg + 2][arow] = __expf(pa0.z - cm0.z);
            As[nb][akg + 3][arow] = __expf(pa0.w - cm0.w);
            As[nb][akg + 4][arow] = __expf(pa1.x - cm1.x);
            As[nb][akg + 5][arow] = __expf(pa1.y - cm1.y);
            As[nb][akg + 6][arow] = __expf(pa1.z - cm1.z);
            As[nb][akg + 7][arow] = __expf(pa1.w - cm1.w);
            pb0.x *= sc; pb0.y *= sc; pb0.z *= sc; pb0.w *= sc;
            pb1.x *= sc; pb1.y *= sc; pb1.z *= sc; pb1.w *= sc;
            *(float4*)&Bs[nb][bkk][bcg] = pb0;
            *(float4*)&Bs[nb][bkk][bcg + 4] = pb1;
        }
        __syncthreads();
    }

#pragma unroll
    for (int i = 0; i < 8; i++) {
        float* orow = g_app + (size_t)b * Sn * C2 + (size_t)(l0 + ty * 8 + i) * C2 + tx * 8;
        ulonglong2 u0, u1;
        u0.x = acc[i][0]; u0.y = acc[i][1];
        u1.x = acc[i][2]; u1.y = acc[i][3];
        *(ulonglong2*)orow = u0;
        *(ulonglong2*)(orow + 4) = u1;
    }
}

// ---------------------------------------------------------------------------
// output conv + residual: out = gamma*(W2[256,128] x appflat[128,4096] + b2) + x
// tile 128o x 128sp, 256 threads, micro 8x8 f32x2, K=128 chunks 16, dbl-buf.
// grid (Sn/128, 2, Bn)
// ---------------------------------------------------------------------------
__global__ __launch_bounds__(256) void out_conv_k(
    const float* __restrict__ x, const float* __restrict__ w2,
    const float* __restrict__ b2, const float* __restrict__ gamma,
    float* __restrict__ out) {
    int b = blockIdx.z, o0 = blockIdx.y * 128, sp0 = blockIdx.x * 128;
    __shared__ __align__(16) float Ws[2][16][132];
    __shared__ __align__(16) float Bs[2][16][128];
    int t = threadIdx.x;

    int wrow = t >> 1, wkg = (t & 1) * 8;
    const float* wsrc = w2 + (size_t)(o0 + wrow) * C2 + wkg;
    int bkk = t >> 4, bsg = (t & 15) * 8;
    const float* asrc = g_app + (size_t)b * Sn * C2 + (size_t)bkk * Sn + sp0 + bsg;

    int ty = t >> 4, tx = t & 15;
    ull acc[8][4];
#pragma unroll
    for (int i = 0; i < 8; i++)
#pragma unroll
        for (int j = 0; j < 4; j++) acc[i][j] = 0ULL;

    // preload chunk 0
    {
        float4 w0 = *(const float4*)(wsrc);
        float4 w1 = *(const float4*)(wsrc + 4);
        Ws[0][wkg + 0][wrow] = w0.x; Ws[0][wkg + 1][wrow] = w0.y;
        Ws[0][wkg + 2][wrow] = w0.z; Ws[0][wkg + 3][wrow] = w0.w;
        Ws[0][wkg + 4][wrow] = w1.x; Ws[0][wkg + 5][wrow] = w1.y;
        Ws[0][wkg + 6][wrow] = w1.z; Ws[0][wkg + 7][wrow] = w1.w;
        *(float4*)&Bs[0][bkk][bsg] = *(const float4*)(asrc);
        *(float4*)&Bs[0][bkk][bsg + 4] = *(const float4*)(asrc + 4);
    }
    __syncthreads();

    for (int ch = 0; ch < 8; ch++) {
        int cb = ch & 1;
        float4 w0, w1, pb0, pb1;
        if (ch < 7) {
            int kc = (ch + 1) * 16;
            w0 = *(const float4*)(wsrc + kc);
            w1 = *(const float4*)(wsrc + kc + 4);
            const float* ap = asrc + (size_t)kc * Sn;
            pb0 = *(const float4*)(ap);
            pb1 = *(const float4*)(ap + 4);
        }
#pragma unroll
        for (int kk = 0; kk < 16; kk++) {
            float4 a0 = *(const float4*)&Ws[cb][kk][ty * 8];
            float4 a1 = *(const float4*)&Ws[cb][kk][ty * 8 + 4];
            ulonglong2 b0 = *(const ulonglong2*)&Bs[cb][kk][tx * 8];
            ulonglong2 b1 = *(const ulonglong2*)&Bs[cb][kk][tx * 8 + 4];
            ull bp[4] = {b0.x, b0.y, b1.x, b1.y};
            float aa[8] = {a0.x, a0.y, a0.z, a0.w, a1.x, a1.y, a1.z, a1.w};
#pragma unroll
            for (int i = 0; i < 8; i++) {
                ull ad = dup2(aa[i]);
#pragma unroll
                for (int j = 0; j < 4; j++) acc[i][j] = ffma2(ad, bp[j], acc[i][j]);
            }
        }
        if (ch < 7) {
            int nb = cb ^ 1;
            Ws[nb][wkg + 0][wrow] = w0.x; Ws[nb][wkg + 1][wrow] = w0.y;
            Ws[nb][wkg + 2][wrow] = w0.z; Ws[nb][wkg + 3][wrow] = w0.w;
            Ws[nb][wkg + 4][wrow] = w1.x; Ws[nb][wkg + 5][wrow] = w1.y;
            Ws[nb][wkg + 6][wrow] = w1.z; Ws[nb][wkg + 7][wrow] = w1.w;
            *(float4*)&Bs[nb][bkk][bsg] = pb0;
            *(float4*)&Bs[nb][bkk][bsg + 4] = pb1;
        }
        __syncthreads();
    }

    float g = gamma[0];
#pragma unroll
    for (int i = 0; i < 8; i++) {
        int o = o0 + ty * 8 + i;
        float bb = b2[o];
        const float* xr = x + (size_t)b * Cc * Sn + (size_t)o * Sn + sp0 + tx * 8;
        float* orow = out + (size_t)b * Cc * Sn + (size_t)o * Sn + sp0 + tx * 8;
        float2 v0 = upk(acc[i][0]), v1 = upk(acc[i][1]);
        float2 v2 = upk(acc[i][2]), v3 = upk(acc[i][3]);
        float4 xa = *(const float4*)(xr);
        float4 xb4 = *(const float4*)(xr + 4);
        float4 r0, r1;
        r0.x = fmaf(g, v0.x + bb, xa.x);
        r0.y = fmaf(g, v0.y + bb, xa.y);
        r0.z = fmaf(g, v1.x + bb, xa.z);
        r0.w = fmaf(g, v1.y + bb, xa.w);
        r1.x = fmaf(g, v2.x + bb, xb4.x);
        r1.y = fmaf(g, v2.y + bb, xb4.y);
        r1.z = fmaf(g, v3.x + bb, xb4.z);
        r1.w = fmaf(g, v3.y + bb, xb4.w);
        *(float4*)(orow) = r0;
        *(float4*)(orow + 4) = r1;
    }
}

// ---------------------------------------------------------------------------
extern "C" void kernel_launch(void* const* d_in, const int* in_sizes, int n_in,
                              void* d_out, int out_size) {
    const float* x   = (const float*)d_in[0];
    const float* qw  = (const float*)d_in[1];
    const float* qb  = (const float*)d_in[2];
    const float* kw  = (const float*)d_in[3];
    const float* kb  = (const float*)d_in[4];
    const float* vw  = (const float*)d_in[5];
    const float* vb  = (const float*)d_in[6];
    const float* v2w = (const float*)d_in[7];
    const float* v2b = (const float*)d_in[8];
    const float* gm  = (const float*)d_in[9];
    float* out = (float*)d_out;

    conv_all_k<<<dim3(32, 3, Bn), 128>>>(x, qw, qb, kw, kb, vw, vb);
    attn_gemm_k<<<dim3(Dn / 128, Sn / 128, Bn), 256>>>();
    stats_k<<<dim3(Dn / 128, Bn), dim3(128, 4)>>>();
    applied_gemm_k<<<dim3(Sn / 128, Bn), 256>>>();
    out_conv_k<<<dim3(Sn / 128, 2, Bn), 256>>>(x, v2w, v2b, gm, out);
}